// round 9
// baseline (speedup 1.0000x reference)
#include <cuda_runtime.h>
#include <cuda_bf16.h>
#include <math.h>

// Problem constants
#define S      2048
#define Hdim   2048
#define KVdim  512
#define NH     32
#define NKV    8
#define HD     64
#define SCALE  0.125f
#define NQKV   3072

// ---------------------------------------------------------------------------
// Scratch (device globals)
// ---------------------------------------------------------------------------
__device__ float g_qkv[S * NQKV];

// tf32 head-major operands for attention.
// g_kt rows are PERMUTED: d -> (d&3)*16 + (d>>3)*2 + ((d>>2)&1)  (K frag pairs)
// g_vt rows are PERMUTED: d -> (d&7)*8 + (d>>3)                  (V frag rows)
__device__ unsigned g_qt[NH * S * HD];
__device__ unsigned g_kt[NKV * S * HD];
__device__ unsigned g_vt[NKV * S * HD];

// bf16 hi/lo pre-split operands for GEMMs
__device__ __nv_bfloat16 s_hs_h[S * Hdim],     s_hs_l[S * Hdim];
__device__ __nv_bfloat16 s_wa_h[NQKV * Hdim],  s_wa_l[NQKV * Hdim];
__device__ __nv_bfloat16 s_wo_h[Hdim * Hdim],  s_wo_l[Hdim * Hdim];
__device__ __nv_bfloat16 s_at_h[S * Hdim],     s_at_l[S * Hdim];

__device__ __forceinline__ unsigned f2tf(float x) {
    unsigned r;
    asm("cvt.rna.tf32.f32 %0, %1;" : "=r"(r) : "f"(x));
    return r;
}

__device__ __forceinline__ void mma_tf32(float d[4], const unsigned a[4], const unsigned b[2]) {
    asm volatile(
        "mma.sync.aligned.m16n8k8.row.col.f32.tf32.tf32.f32 "
        "{%0,%1,%2,%3}, {%4,%5,%6,%7}, {%8,%9}, {%0,%1,%2,%3};"
        : "+f"(d[0]), "+f"(d[1]), "+f"(d[2]), "+f"(d[3])
        : "r"(a[0]), "r"(a[1]), "r"(a[2]), "r"(a[3]), "r"(b[0]), "r"(b[1]));
}

__device__ __forceinline__ void mma_bf16(float d[4], const unsigned a[4],
                                         unsigned b0, unsigned b1) {
    asm volatile(
        "mma.sync.aligned.m16n8k16.row.col.f32.bf16.bf16.f32 "
        "{%0,%1,%2,%3}, {%4,%5,%6,%7}, {%8,%9}, {%0,%1,%2,%3};"
        : "+f"(d[0]), "+f"(d[1]), "+f"(d[2]), "+f"(d[3])
        : "r"(a[0]), "r"(a[1]), "r"(a[2]), "r"(a[3]), "r"(b0), "r"(b1));
}

#define LDSM4(r, a)                                                          \
    asm volatile("ldmatrix.sync.aligned.m8n8.x4.shared.b16 {%0,%1,%2,%3}, [%4];" \
        : "=r"((r)[0]), "=r"((r)[1]), "=r"((r)[2]), "=r"((r)[3]) : "r"(a))

__device__ __forceinline__ unsigned bf2u(__nv_bfloat162 v) { return *(unsigned*)&v; }

// ---------------------------------------------------------------------------
// ONE fused bf16 hi/lo split over all 5 input tensors
// ---------------------------------------------------------------------------
#define HS4  (S * Hdim / 4)
#define W4   (Hdim * Hdim / 4)
#define WK4  (KVdim * Hdim / 4)
#define TOT4 (HS4 + W4 + 2 * WK4 + W4)

__device__ __forceinline__ void split_store(float4 v, uint2* h, uint2* l, int i)
{
    __nv_bfloat162 h0 = __floats2bfloat162_rn(v.x, v.y);
    __nv_bfloat162 h1 = __floats2bfloat162_rn(v.z, v.w);
    __nv_bfloat162 l0 = __floats2bfloat162_rn(v.x - __bfloat162float(h0.x),
                                              v.y - __bfloat162float(h0.y));
    __nv_bfloat162 l1 = __floats2bfloat162_rn(v.z - __bfloat162float(h1.x),
                                              v.w - __bfloat162float(h1.y));
    h[i] = make_uint2(bf2u(h0), bf2u(h1));
    l[i] = make_uint2(bf2u(l0), bf2u(l1));
}

__global__ __launch_bounds__(256) void split_all(
    const float4* __restrict__ hs, const float4* __restrict__ wq,
    const float4* __restrict__ wk, const float4* __restrict__ wv,
    const float4* __restrict__ wo)
{
    int i = blockIdx.x * blockDim.x + threadIdx.x;
    if (i >= TOT4) return;

    if (i < HS4) {
        split_store(hs[i], (uint2*)s_hs_h, (uint2*)s_hs_l, i);
    } else if (i < HS4 + W4) {
        int j = i - HS4;
        split_store(wq[j], (uint2*)s_wa_h, (uint2*)s_wa_l, j);
    } else if (i < HS4 + W4 + WK4) {
        int j = i - HS4 - W4;
        split_store(wk[j], (uint2*)s_wa_h + W4, (uint2*)s_wa_l + W4, j);
    } else if (i < HS4 + W4 + 2 * WK4) {
        int j = i - HS4 - W4 - WK4;
        split_store(wv[j], (uint2*)s_wa_h + W4 + WK4, (uint2*)s_wa_l + W4 + WK4, j);
    } else {
        int j = i - HS4 - W4 - 2 * WK4;
        split_store(wo[j], (uint2*)s_wo_h, (uint2*)s_wo_l, j);
    }
}

// ---------------------------------------------------------------------------
// bf16x3 GEMM (unchanged from R8-passing version)
// ---------------------------------------------------------------------------
#define ROWU 20
#define ARRU (128 * ROWU)
#define STGU (4 * ARRU)

__global__ __launch_bounds__(256, 2) void gemm_bf16x3_nt(
    const __nv_bfloat16* __restrict__ Agh, const __nv_bfloat16* __restrict__ Agl,
    const __nv_bfloat16* __restrict__ Bgh, const __nv_bfloat16* __restrict__ Bgl,
    float* __restrict__ C, int M, int N, int K)
{
    extern __shared__ unsigned sm[];

    int tid = threadIdx.x, wid = tid >> 5, lane = tid & 31;
    int wm = (wid & 3) * 32, wn = (wid >> 2) * 64;
    int bm = blockIdx.y * 128, bn = blockIdx.x * 128;
    int g = lane >> 2, tg = lane & 3;
    int lr = tid >> 2, lch = tid & 3;

    unsigned smem_base = (unsigned)__cvta_generic_to_shared(sm);

    unsigned a_row = (unsigned)(wm + (lane & 15)) * ROWU * 4 + (lane >> 4) * 16;
    unsigned b_row = (unsigned)(wn + (lane & 7) + ((lane >> 4) & 1) * 8) * ROWU * 4
                   + ((lane >> 3) & 1) * 16;

    float acc[2][8][4];
#pragma unroll
    for (int i = 0; i < 2; i++)
#pragma unroll
        for (int j = 0; j < 8; j++)
#pragma unroll
            for (int c = 0; c < 4; c++) acc[i][j][c] = 0.f;

    auto issue = [&](int s, int k0) {
#pragma unroll
        for (int p = 0; p < 2; p++) {
            int row = lr + p * 64;
            unsigned soff = smem_base + (unsigned)(s * STGU + row * ROWU + lch * 4) * 4;
            const __nv_bfloat16* ga = Agh + (size_t)(bm + row) * K + k0 + lch * 8;
            asm volatile("cp.async.cg.shared.global [%0], [%1], 16;"
                         :: "r"(soff), "l"(ga));
            ga = Agl + (size_t)(bm + row) * K + k0 + lch * 8;
            asm volatile("cp.async.cg.shared.global [%0], [%1], 16;"
                         :: "r"(soff + ARRU * 4), "l"(ga));
            const __nv_bfloat16* gb = Bgh + (size_t)(bn + row) * K + k0 + lch * 8;
            asm volatile("cp.async.cg.shared.global [%0], [%1], 16;"
                         :: "r"(soff + 2 * ARRU * 4), "l"(gb));
            gb = Bgl + (size_t)(bn + row) * K + k0 + lch * 8;
            asm volatile("cp.async.cg.shared.global [%0], [%1], 16;"
                         :: "r"(soff + 3 * ARRU * 4), "l"(gb));
        }
    };

    int nk = K / 32;
    issue(0, 0);
    asm volatile("cp.async.commit_group;");

    for (int it = 0; it < nk; it++) {
        if (it + 1 < nk) {
            issue((it + 1) & 1, (it + 1) * 32);
            asm volatile("cp.async.commit_group;");
            asm volatile("cp.async.wait_group 1;");
        } else {
            asm volatile("cp.async.wait_group 0;");
        }
        __syncthreads();

        unsigned buf = smem_base + (unsigned)((it & 1) * STGU) * 4;

#pragma unroll
        for (int ks = 0; ks < 2; ks++) {
            unsigned ah[2][4], al[2][4];
#pragma unroll
            for (int tm = 0; tm < 2; tm++) {
                unsigned aaddr = buf + a_row + (unsigned)(tm * 16 * ROWU * 4) + ks * 32;
                LDSM4(ah[tm], aaddr);
                LDSM4(al[tm], aaddr + ARRU * 4);
            }
#pragma unroll
            for (int ntp = 0; ntp < 4; ntp++) {
                unsigned bh[4], bl[4];
                unsigned baddr = buf + 2u * ARRU * 4 + b_row
                               + (unsigned)(ntp * 16 * ROWU * 4) + ks * 32;
                LDSM4(bh, baddr);
                LDSM4(bl, baddr + ARRU * 4);
#pragma unroll
                for (int tm = 0; tm < 2; tm++) {
                    mma_bf16(acc[tm][2 * ntp],     ah[tm], bh[0], bh[1]);
                    mma_bf16(acc[tm][2 * ntp],     al[tm], bh[0], bh[1]);
                    mma_bf16(acc[tm][2 * ntp],     ah[tm], bl[0], bl[1]);
                    mma_bf16(acc[tm][2 * ntp + 1], ah[tm], bh[2], bh[3]);
                    mma_bf16(acc[tm][2 * ntp + 1], al[tm], bh[2], bh[3]);
                    mma_bf16(acc[tm][2 * ntp + 1], ah[tm], bl[2], bl[3]);
                }
            }
        }
        __syncthreads();
    }

#pragma unroll
    for (int tm = 0; tm < 2; tm++)
#pragma unroll
        for (int nt = 0; nt < 8; nt++) {
            int row = bm + wm + tm * 16 + g;
            int col = bn + wn + nt * 8 + 2 * tg;
            *(float2*)(C + (size_t)row * N + col) =
                make_float2(acc[tm][nt][0], acc[tm][nt][1]);
            *(float2*)(C + (size_t)(row + 8) * N + col) =
                make_float2(acc[tm][nt][2], acc[tm][nt][3]);
        }
}

// ---------------------------------------------------------------------------
// RoPE + tf32 conversion; K and V rows written PRE-PERMUTED for vectorized
// fragment loads in the attention kernel.
// ---------------------------------------------------------------------------
__device__ __forceinline__ int kperm(int d) {
    return (d & 3) * 16 + ((d >> 3) & 7) * 2 + ((d >> 2) & 1);
}
__device__ __forceinline__ int vperm(int d) {
    return (d & 7) * 8 + (d >> 3);
}

__global__ void rope_conv_kernel()
{
    int idx = blockIdx.x * blockDim.x + threadIdx.x;
    const int total = S * (NH + 2 * NKV) * 32;
    if (idx >= total) return;

    int i  = idx & 31;
    int r  = idx >> 5;
    int hs = r % (NH + 2 * NKV);
    int s  = r / (NH + 2 * NKV);

    if (hs < NH + NKV) {
        float inv_freq = __powf(10000.0f, -(float)i / 32.0f);
        float angle = (float)s * inv_freq;
        float c, sn;
        sincosf(angle, &sn, &c);

        if (hs < NH) {
            const float* base = g_qkv + (size_t)s * NQKV + hs * HD;
            float x1 = base[i], x2 = base[i + 32];
            unsigned* dst = g_qt + ((size_t)hs * S + s) * HD;
            dst[i]      = f2tf((x1 * c - x2 * sn) * SCALE);
            dst[i + 32] = f2tf((x2 * c + x1 * sn) * SCALE);
        } else {
            int kvh = hs - NH;
            const float* base = g_qkv + (size_t)s * NQKV + 2048 + kvh * HD;
            float x1 = base[i], x2 = base[i + 32];
            unsigned* dst = g_kt + ((size_t)kvh * S + s) * HD;
            dst[kperm(i)]      = f2tf(x1 * c - x2 * sn);
            dst[kperm(i + 32)] = f2tf(x2 * c + x1 * sn);
        }
    } else {
        int kvh = hs - NH - NKV;
        const float* base = g_qkv + (size_t)s * NQKV + 2560 + kvh * HD;
        unsigned* dst = g_vt + ((size_t)kvh * S + s) * HD;
        dst[vperm(i)]      = f2tf(base[i]);
        dst[vperm(i + 32)] = f2tf(base[i + 32]);
    }
}

// ---------------------------------------------------------------------------
// Tensor-core flash attention, tf32, vectorized (LDS.128) K/V fragment loads.
// grid (S/128, NH), 256 threads (8 warps x 16 q-rows).
// K/V smem stride 76 u32 (304B, 16B-aligned, balanced banks).
// ---------------------------------------------------------------------------
#define KSTR 76
#define VSTR 76
#define QSTR 68
#define KBUF (64 * KSTR)
#define VBUF (64 * VSTR)
#define BUFU (KBUF + VBUF)
#define QPOFF (2 * BUFU)
#define ATTN_SMEM_B ((2 * BUFU + 128 * QSTR) * 4)   // 112640 B

__global__ __launch_bounds__(256) void flash_attn_tc()
{
    extern __shared__ unsigned sm[];

    int h   = blockIdx.y;
    int kvh = h >> 2;
    int q0  = ((int)gridDim.x - 1 - (int)blockIdx.x) * 128;
    int tid = threadIdx.x;
    int w    = tid >> 5;
    int lane = tid & 31;
    int g    = lane >> 2;
    int tg   = lane & 3;

    unsigned smem_base = (unsigned)__cvta_generic_to_shared(sm);
    unsigned* QP = sm + QPOFF;

    {
        const unsigned* qsrc = g_qt + ((size_t)h * S + q0) * HD;
#pragma unroll
        for (int e2 = 0; e2 < 8; e2++) {
            int e = tid + e2 * 256;
            int rr = e >> 4, c = (e & 15) * 4;
            *(uint4*)(QP + rr * QSTR + c) = *(const uint4*)(qsrc + rr * 64 + c);
        }
    }
    __syncthreads();

    unsigned qa[8][4];
#pragma unroll
    for (int kt = 0; kt < 8; kt++) {
        int base = (w * 16 + g) * QSTR + kt * 8 + tg;
        qa[kt][0] = QP[base];
        qa[kt][1] = QP[base + 8 * QSTR];
        qa[kt][2] = QP[base + 4];
        qa[kt][3] = QP[base + 8 * QSTR + 4];
    }

    const unsigned* kg = g_kt + (size_t)kvh * S * HD;
    const unsigned* vg = g_vt + (size_t)kvh * S * HD;

    auto stage = [&](int buf, int kk) {
        unsigned koff = smem_base + (unsigned)(buf * BUFU) * 4;
        unsigned voff = koff + KBUF * 4;
#pragma unroll
        for (int e2 = 0; e2 < 4; e2++) {
            int e = tid + e2 * 256;
            int rr = e >> 4, c = (e & 15) * 4;
            const unsigned* gk = kg + (size_t)(kk + rr) * HD + c;
            const unsigned* gv = vg + (size_t)(kk + rr) * HD + c;
            asm volatile("cp.async.cg.shared.global [%0], [%1], 16;"
                         :: "r"(koff + (unsigned)(rr * KSTR + c) * 4), "l"(gk));
            asm volatile("cp.async.cg.shared.global [%0], [%1], 16;"
                         :: "r"(voff + (unsigned)(rr * VSTR + c) * 4), "l"(gv));
        }
    };

    float oacc[8][4];
#pragma unroll
    for (int nt = 0; nt < 8; nt++)
#pragma unroll
        for (int c = 0; c < 4; c++) oacc[nt][c] = 0.f;

    float m0 = -1e30f, m1 = -1e30f, l0 = 0.f, l1 = 0.f;
    int row0 = q0 + w * 16 + g;
    int row1 = row0 + 8;
    unsigned* Pw = QP + w * 16 * QSTR;

    int nch = (q0 + 128) / 64;
    stage(0, 0);
    asm volatile("cp.async.commit_group;");

    for (int it = 0; it < nch; it++) {
        int kk = it * 64;
        if (it + 1 < nch) {
            stage((it + 1) & 1, kk + 64);
            asm volatile("cp.async.commit_group;");
            asm volatile("cp.async.wait_group 1;");
        } else {
            asm volatile("cp.async.wait_group 0;");
        }
        __syncthreads();

        const unsigned* Ks = sm + (it & 1) * BUFU;
        const unsigned* Vs = Ks + KBUF;

        // S = Q K^T  — K fragments via vectorized uint4 loads (permuted rows)
        float sacc[8][4];
#pragma unroll
        for (int nt = 0; nt < 8; nt++) {
#pragma unroll
            for (int c = 0; c < 4; c++) sacc[nt][c] = 0.f;
            int krow = (nt * 8 + g) * KSTR + tg * 16;
#pragma unroll
            for (int p = 0; p < 4; p++) {
                uint4 kv = *(const uint4*)(Ks + krow + p * 4);
                unsigned b0[2] = { kv.x, kv.y };
                mma_tf32(sacc[nt], qa[2 * p], b0);
                unsigned b1[2] = { kv.z, kv.w };
                mma_tf32(sacc[nt], qa[2 * p + 1], b1);
            }
        }

        if (kk + 63 > row0) {
#pragma unroll
            for (int nt = 0; nt < 8; nt++) {
                int col = kk + nt * 8 + 2 * tg;
                if (col     > row0) sacc[nt][0] = -1e30f;
                if (col + 1 > row0) sacc[nt][1] = -1e30f;
                if (col     > row1) sacc[nt][2] = -1e30f;
                if (col + 1 > row1) sacc[nt][3] = -1e30f;
            }
        }

        float mc0 = -1e30f, mc1 = -1e30f;
#pragma unroll
        for (int nt = 0; nt < 8; nt++) {
            mc0 = fmaxf(mc0, fmaxf(sacc[nt][0], sacc[nt][1]));
            mc1 = fmaxf(mc1, fmaxf(sacc[nt][2], sacc[nt][3]));
        }
        mc0 = fmaxf(mc0, __shfl_xor_sync(0xFFFFFFFFu, mc0, 1));
        mc0 = fmaxf(mc0, __shfl_xor_sync(0xFFFFFFFFu, mc0, 2));
        mc1 = fmaxf(mc1, __shfl_xor_sync(0xFFFFFFFFu, mc1, 1));
        mc1 = fmaxf(mc1, __shfl_xor_sync(0xFFFFFFFFu, mc1, 2));

        float mn0 = fmaxf(m0, mc0), mn1 = fmaxf(m1, mc1);
        float cr0 = __expf(m0 - mn0), cr1 = __expf(m1 - mn1);
        l0 *= cr0; l1 *= cr1;
#pragma unroll
        for (int nt = 0; nt < 8; nt++) {
            oacc[nt][0] *= cr0; oacc[nt][1] *= cr0;
            oacc[nt][2] *= cr1; oacc[nt][3] *= cr1;
        }
        m0 = mn0; m1 = mn1;

#pragma unroll
        for (int nt = 0; nt < 8; nt++) {
            float p0 = __expf(sacc[nt][0] - mn0);
            float p1 = __expf(sacc[nt][1] - mn0);
            float p2 = __expf(sacc[nt][2] - mn1);
            float p3 = __expf(sacc[nt][3] - mn1);
            l0 += p0 + p1;
            l1 += p2 + p3;
            int pb = g * QSTR + nt * 8 + 2 * tg;
            *(uint2*)(Pw + pb)            = make_uint2(f2tf(p0), f2tf(p1));
            *(uint2*)(Pw + pb + 8 * QSTR) = make_uint2(f2tf(p2), f2tf(p3));
        }
        __syncwarp();

        // O += P V  — V fragments via vectorized uint4 loads (permuted rows)
#pragma unroll
        for (int kt = 0; kt < 8; kt++) {
            unsigned pa[4];
            int pb = g * QSTR + kt * 8 + tg;
            pa[0] = Pw[pb];
            pa[1] = Pw[pb + 8 * QSTR];
            pa[2] = Pw[pb + 4];
            pa[3] = Pw[pb + 8 * QSTR + 4];

            int vr0 = (kt * 8 + tg) * VSTR + g * 8;
            uint4 v0a = *(const uint4*)(Vs + vr0);
            uint4 v0b = *(const uint4*)(Vs + vr0 + 4);
            uint4 v1a = *(const uint4*)(Vs + vr0 + 4 * VSTR);
            uint4 v1b = *(const uint4*)(Vs + vr0 + 4 * VSTR + 4);

            unsigned b[2];
            b[0] = v0a.x; b[1] = v1a.x; mma_tf32(oacc[0], pa, b);
            b[0] = v0a.y; b[1] = v1a.y; mma_tf32(oacc[1], pa, b);
            b[0] = v0a.z; b[1] = v1a.z; mma_tf32(oacc[2], pa, b);
            b[0] = v0a.w; b[1] = v1a.w; mma_tf32(oacc[3], pa, b);
            b[0] = v0b.x; b[1] = v1b.x; mma_tf32(oacc[4], pa, b);
            b[0] = v0b.y; b[1] = v1b.y; mma_tf32(oacc[5], pa, b);
            b[0] = v0b.z; b[1] = v1b.z; mma_tf32(oacc[6], pa, b);
            b[0] = v0b.w; b[1] = v1b.w; mma_tf32(oacc[7], pa, b);
        }
        __syncthreads();
    }

    l0 += __shfl_xor_sync(0xFFFFFFFFu, l0, 1);
    l0 += __shfl_xor_sync(0xFFFFFFFFu, l0, 2);
    l1 += __shfl_xor_sync(0xFFFFFFFFu, l1, 1);
    l1 += __shfl_xor_sync(0xFFFFFFFFu, l1, 2);
    float inv0 = 1.f / l0, inv1 = 1.f / l1;

#pragma unroll
    for (int nt = 0; nt < 8; nt++) {
        int col = h * HD + nt * 8 + 2 * tg;
        {
            float a0 = oacc[nt][0] * inv0, a1 = oacc[nt][1] * inv0;
            __nv_bfloat162 hv = __floats2bfloat162_rn(a0, a1);
            __nv_bfloat162 lv = __floats2bfloat162_rn(a0 - __bfloat162float(hv.x),
                                                      a1 - __bfloat162float(hv.y));
            *(__nv_bfloat162*)(s_at_h + (size_t)row0 * Hdim + col) = hv;
            *(__nv_bfloat162*)(s_at_l + (size_t)row0 * Hdim + col) = lv;
        }
        {
            float a0 = oacc[nt][2] * inv1, a1 = oacc[nt][3] * inv1;
            __nv_bfloat162 hv = __floats2bfloat162_rn(a0, a1);
            __nv_bfloat162 lv = __floats2bfloat162_rn(a0 - __bfloat162float(hv.x),
                                                      a1 - __bfloat162float(hv.y));
            *(__nv_bfloat162*)(s_at_h + (size_t)row1 * Hdim + col) = hv;
            *(__nv_bfloat162*)(s_at_l + (size_t)row1 * Hdim + col) = lv;
        }
    }
}

// ---------------------------------------------------------------------------
// Launch
// ---------------------------------------------------------------------------
extern "C" void kernel_launch(void* const* d_in, const int* in_sizes, int n_in,
                              void* d_out, int out_size)
{
    const float* hs = (const float*)d_in[0];
    const float* Wq = (const float*)d_in[1];
    const float* Wk = (const float*)d_in[2];
    const float* Wv = (const float*)d_in[3];
    const float* Wo = (const float*)d_in[4];
    float* out = (float*)d_out;

    float* qkvp;
    __nv_bfloat16 *hsh, *hsl, *wah, *wal, *woh, *wol, *ath, *atl;
    cudaGetSymbolAddress((void**)&qkvp, g_qkv);
    cudaGetSymbolAddress((void**)&hsh, s_hs_h);  cudaGetSymbolAddress((void**)&hsl, s_hs_l);
    cudaGetSymbolAddress((void**)&wah, s_wa_h);  cudaGetSymbolAddress((void**)&wal, s_wa_l);
    cudaGetSymbolAddress((void**)&woh, s_wo_h);  cudaGetSymbolAddress((void**)&wol, s_wo_l);
    cudaGetSymbolAddress((void**)&ath, s_at_h);  cudaGetSymbolAddress((void**)&atl, s_at_l);

    const int gemm_smem = 2 * STGU * 4;
    cudaFuncSetAttribute(gemm_bf16x3_nt,
                         cudaFuncAttributeMaxDynamicSharedMemorySize, gemm_smem);
    cudaFuncSetAttribute(flash_attn_tc,
                         cudaFuncAttributeMaxDynamicSharedMemorySize, ATTN_SMEM_B);

    split_all<<<(TOT4 + 255) / 256, 256>>>(
        (const float4*)hs, (const float4*)Wq, (const float4*)Wk,
        (const float4*)Wv, (const float4*)Wo);

    gemm_bf16x3_nt<<<dim3(NQKV / 128, S / 128), 256, gemm_smem>>>(
        hsh, hsl, wah, wal, qkvp, S, NQKV, Hdim);

    {
        int total = S * (NH + 2 * NKV) * 32;
        rope_conv_kernel<<<(total + 255) / 256, 256>>>();
    }

    flash_attn_tc<<<dim3(S / 128, NH), 256, ATTN_SMEM_B>>>();

    gemm_bf16x3_nt<<<dim3(Hdim / 128, S / 128), 256, gemm_smem>>>(
        ath, atl, woh, wol, out, S, Hdim, Hdim);
}

// round 10
// speedup vs baseline: 1.3826x; 1.3826x over previous
#include <cuda_runtime.h>
#include <cuda_bf16.h>
#include <cuda_fp16.h>
#include <math.h>

// Problem constants
#define S      2048
#define Hdim   2048
#define KVdim  512
#define NH     32
#define NKV    8
#define HD     64
#define SCALE  0.125f
#define NQKV   3072

// ---------------------------------------------------------------------------
// Scratch (device globals)
// ---------------------------------------------------------------------------
__device__ float g_qkv[S * NQKV];

// tf32 head-major operands for attention (plain layout, R8 style)
__device__ unsigned g_qt[NH * S * HD];
__device__ unsigned g_kt[NKV * S * HD];
__device__ unsigned g_vt[NKV * S * HD];

// fp16 split operands: activations hi+lo, weights hi only
__device__ __half s_hs_h[S * Hdim],    s_hs_l[S * Hdim];
__device__ __half s_wa_h[NQKV * Hdim];                    // Wq|Wk|Wv hi
__device__ __half s_wo_h[Hdim * Hdim];
__device__ __half s_at_h[S * Hdim],    s_at_l[S * Hdim];

__device__ __forceinline__ unsigned f2tf(float x) {
    unsigned r;
    asm("cvt.rna.tf32.f32 %0, %1;" : "=r"(r) : "f"(x));
    return r;
}

__device__ __forceinline__ void mma_tf32(float d[4], const unsigned a[4], const unsigned b[2]) {
    asm volatile(
        "mma.sync.aligned.m16n8k8.row.col.f32.tf32.tf32.f32 "
        "{%0,%1,%2,%3}, {%4,%5,%6,%7}, {%8,%9}, {%0,%1,%2,%3};"
        : "+f"(d[0]), "+f"(d[1]), "+f"(d[2]), "+f"(d[3])
        : "r"(a[0]), "r"(a[1]), "r"(a[2]), "r"(a[3]), "r"(b[0]), "r"(b[1]));
}

__device__ __forceinline__ void mma_f16(float d[4], const unsigned a[4],
                                        unsigned b0, unsigned b1) {
    asm volatile(
        "mma.sync.aligned.m16n8k16.row.col.f32.f16.f16.f32 "
        "{%0,%1,%2,%3}, {%4,%5,%6,%7}, {%8,%9}, {%0,%1,%2,%3};"
        : "+f"(d[0]), "+f"(d[1]), "+f"(d[2]), "+f"(d[3])
        : "r"(a[0]), "r"(a[1]), "r"(a[2]), "r"(a[3]), "r"(b0), "r"(b1));
}

#define LDSM4(r, a)                                                          \
    asm volatile("ldmatrix.sync.aligned.m8n8.x4.shared.b16 {%0,%1,%2,%3}, [%4];" \
        : "=r"((r)[0]), "=r"((r)[1]), "=r"((r)[2]), "=r"((r)[3]) : "r"(a))

__device__ __forceinline__ unsigned h2u(__half2 v) { return *(unsigned*)&v; }

// ---------------------------------------------------------------------------
// ONE fused fp16 split: hs -> hi+lo, weights -> hi only
// ---------------------------------------------------------------------------
#define HS4  (S * Hdim / 4)
#define W4   (Hdim * Hdim / 4)
#define WK4  (KVdim * Hdim / 4)
#define TOT4 (HS4 + W4 + 2 * WK4 + W4)

__device__ __forceinline__ void split_hl(float4 v, uint2* h, uint2* l, int i)
{
    __half2 h0 = __floats2half2_rn(v.x, v.y);
    __half2 h1 = __floats2half2_rn(v.z, v.w);
    __half2 l0 = __floats2half2_rn(v.x - __low2float(h0), v.y - __high2float(h0));
    __half2 l1 = __floats2half2_rn(v.z - __low2float(h1), v.w - __high2float(h1));
    h[i] = make_uint2(h2u(h0), h2u(h1));
    l[i] = make_uint2(h2u(l0), h2u(l1));
}

__device__ __forceinline__ void cvt_h(float4 v, uint2* h, int i)
{
    __half2 h0 = __floats2half2_rn(v.x, v.y);
    __half2 h1 = __floats2half2_rn(v.z, v.w);
    h[i] = make_uint2(h2u(h0), h2u(h1));
}

__global__ __launch_bounds__(256) void split_all(
    const float4* __restrict__ hs, const float4* __restrict__ wq,
    const float4* __restrict__ wk, const float4* __restrict__ wv,
    const float4* __restrict__ wo)
{
    int i = blockIdx.x * blockDim.x + threadIdx.x;
    if (i >= TOT4) return;

    if (i < HS4) {
        split_hl(hs[i], (uint2*)s_hs_h, (uint2*)s_hs_l, i);
    } else if (i < HS4 + W4) {
        int j = i - HS4;
        cvt_h(wq[j], (uint2*)s_wa_h, j);
    } else if (i < HS4 + W4 + WK4) {
        int j = i - HS4 - W4;
        cvt_h(wk[j], (uint2*)s_wa_h + W4, j);
    } else if (i < HS4 + W4 + 2 * WK4) {
        int j = i - HS4 - W4 - WK4;
        cvt_h(wv[j], (uint2*)s_wa_h + W4 + WK4, j);
    } else {
        int j = i - HS4 - W4 - 2 * WK4;
        cvt_h(wo[j], (uint2*)s_wo_h, j);
    }
}

// ---------------------------------------------------------------------------
// fp16x2 GEMM, cp.async double-buffered, ldmatrix fragment loads.
// C[M,N] = (Ah+Al)[M,K] * Bh[N,K]^T.  128x128 tile, BK=32, 256 threads.
// 3 staged arrays per buffer: Ah | Al | Bh.
// ---------------------------------------------------------------------------
#define ROWU 20
#define ARRU (128 * ROWU)
#define STG3 (3 * ARRU)

__global__ __launch_bounds__(256, 2) void gemm_f16x2_nt(
    const __half* __restrict__ Agh, const __half* __restrict__ Agl,
    const __half* __restrict__ Bgh,
    float* __restrict__ C, int M, int N, int K)
{
    extern __shared__ unsigned sm[];

    int tid = threadIdx.x, wid = tid >> 5, lane = tid & 31;
    int wm = (wid & 3) * 32, wn = (wid >> 2) * 64;
    int bm = blockIdx.y * 128, bn = blockIdx.x * 128;
    int g = lane >> 2, tg = lane & 3;
    int lr = tid >> 2, lch = tid & 3;

    unsigned smem_base = (unsigned)__cvta_generic_to_shared(sm);

    unsigned a_row = (unsigned)(wm + (lane & 15)) * ROWU * 4 + (lane >> 4) * 16;
    unsigned b_row = (unsigned)(wn + (lane & 7) + ((lane >> 4) & 1) * 8) * ROWU * 4
                   + ((lane >> 3) & 1) * 16;

    float acc[2][8][4];
#pragma unroll
    for (int i = 0; i < 2; i++)
#pragma unroll
        for (int j = 0; j < 8; j++)
#pragma unroll
            for (int c = 0; c < 4; c++) acc[i][j][c] = 0.f;

    auto issue = [&](int s, int k0) {
#pragma unroll
        for (int p = 0; p < 2; p++) {
            int row = lr + p * 64;
            unsigned soff = smem_base + (unsigned)(s * STG3 + row * ROWU + lch * 4) * 4;
            const __half* ga = Agh + (size_t)(bm + row) * K + k0 + lch * 8;
            asm volatile("cp.async.cg.shared.global [%0], [%1], 16;"
                         :: "r"(soff), "l"(ga));
            ga = Agl + (size_t)(bm + row) * K + k0 + lch * 8;
            asm volatile("cp.async.cg.shared.global [%0], [%1], 16;"
                         :: "r"(soff + ARRU * 4), "l"(ga));
            const __half* gb = Bgh + (size_t)(bn + row) * K + k0 + lch * 8;
            asm volatile("cp.async.cg.shared.global [%0], [%1], 16;"
                         :: "r"(soff + 2 * ARRU * 4), "l"(gb));
        }
    };

    int nk = K / 32;
    issue(0, 0);
    asm volatile("cp.async.commit_group;");

    for (int it = 0; it < nk; it++) {
        if (it + 1 < nk) {
            issue((it + 1) & 1, (it + 1) * 32);
            asm volatile("cp.async.commit_group;");
            asm volatile("cp.async.wait_group 1;");
        } else {
            asm volatile("cp.async.wait_group 0;");
        }
        __syncthreads();

        unsigned buf = smem_base + (unsigned)((it & 1) * STG3) * 4;

#pragma unroll
        for (int ks = 0; ks < 2; ks++) {
            unsigned ah[2][4], al[2][4];
#pragma unroll
            for (int tm = 0; tm < 2; tm++) {
                unsigned aaddr = buf + a_row + (unsigned)(tm * 16 * ROWU * 4) + ks * 32;
                LDSM4(ah[tm], aaddr);
                LDSM4(al[tm], aaddr + ARRU * 4);
            }
#pragma unroll
            for (int ntp = 0; ntp < 4; ntp++) {
                unsigned bh[4];
                unsigned baddr = buf + 2u * ARRU * 4 + b_row
                               + (unsigned)(ntp * 16 * ROWU * 4) + ks * 32;
                LDSM4(bh, baddr);
#pragma unroll
                for (int tm = 0; tm < 2; tm++) {
                    mma_f16(acc[tm][2 * ntp],     ah[tm], bh[0], bh[1]);
                    mma_f16(acc[tm][2 * ntp],     al[tm], bh[0], bh[1]);
                    mma_f16(acc[tm][2 * ntp + 1], ah[tm], bh[2], bh[3]);
                    mma_f16(acc[tm][2 * ntp + 1], al[tm], bh[2], bh[3]);
                }
            }
        }
        __syncthreads();
    }

#pragma unroll
    for (int tm = 0; tm < 2; tm++)
#pragma unroll
        for (int nt = 0; nt < 8; nt++) {
            int row = bm + wm + tm * 16 + g;
            int col = bn + wn + nt * 8 + 2 * tg;
            *(float2*)(C + (size_t)row * N + col) =
                make_float2(acc[tm][nt][0], acc[tm][nt][1]);
            *(float2*)(C + (size_t)(row + 8) * N + col) =
                make_float2(acc[tm][nt][2], acc[tm][nt][3]);
        }
}

// ---------------------------------------------------------------------------
// RoPE + tf32 conversion into head-major attention operands (R8 layout).
// ---------------------------------------------------------------------------
__global__ void rope_conv_kernel()
{
    int idx = blockIdx.x * blockDim.x + threadIdx.x;
    const int total = S * (NH + 2 * NKV) * 32;
    if (idx >= total) return;

    int i  = idx & 31;
    int r  = idx >> 5;
    int hs = r % (NH + 2 * NKV);
    int s  = r / (NH + 2 * NKV);

    if (hs < NH + NKV) {
        float inv_freq = __powf(10000.0f, -(float)i / 32.0f);
        float angle = (float)s * inv_freq;
        float c, sn;
        sincosf(angle, &sn, &c);

        if (hs < NH) {
            const float* base = g_qkv + (size_t)s * NQKV + hs * HD;
            float x1 = base[i], x2 = base[i + 32];
            unsigned* dst = g_qt + ((size_t)hs * S + s) * HD;
            dst[i]      = f2tf((x1 * c - x2 * sn) * SCALE);
            dst[i + 32] = f2tf((x2 * c + x1 * sn) * SCALE);
        } else {
            int kvh = hs - NH;
            const float* base = g_qkv + (size_t)s * NQKV + 2048 + kvh * HD;
            float x1 = base[i], x2 = base[i + 32];
            unsigned* dst = g_kt + ((size_t)kvh * S + s) * HD;
            dst[i]      = f2tf(x1 * c - x2 * sn);
            dst[i + 32] = f2tf(x2 * c + x1 * sn);
        }
    } else {
        int kvh = hs - NH - NKV;
        const float* base = g_qkv + (size_t)s * NQKV + 2560 + kvh * HD;
        unsigned* dst = g_vt + ((size_t)kvh * S + s) * HD;
        dst[i]      = f2tf(base[i]);
        dst[i + 32] = f2tf(base[i + 32]);
    }
}

// ---------------------------------------------------------------------------
// Tensor-core flash attention — EXACT R8 structure (regs=128, 2 CTA/SM),
// epilogue writes fp16 hi/lo.
// ---------------------------------------------------------------------------
#define KSTR 68
#define VSTR 72
#define KBUF (64 * KSTR)
#define VBUF (64 * VSTR)
#define BUFU (KBUF + VBUF)
#define QPOFF (2 * BUFU)
#define ATTN_SMEM_B ((2 * BUFU + 128 * KSTR) * 4)

__global__ __launch_bounds__(256) void flash_attn_tc()
{
    extern __shared__ unsigned sm[];

    int h   = blockIdx.y;
    int kvh = h >> 2;
    int q0  = ((int)gridDim.x - 1 - (int)blockIdx.x) * 128;
    int tid = threadIdx.x;
    int w    = tid >> 5;
    int lane = tid & 31;
    int g    = lane >> 2;
    int tg   = lane & 3;

    unsigned smem_base = (unsigned)__cvta_generic_to_shared(sm);
    unsigned* QP = sm + QPOFF;

    {
        const unsigned* qsrc = g_qt + ((size_t)h * S + q0) * HD;
#pragma unroll
        for (int e2 = 0; e2 < 8; e2++) {
            int e = tid + e2 * 256;
            int rr = e >> 4, c = (e & 15) * 4;
            *(uint4*)(QP + rr * KSTR + c) = *(const uint4*)(qsrc + rr * 64 + c);
        }
    }
    __syncthreads();

    unsigned qa[8][4];
#pragma unroll
    for (int kt = 0; kt < 8; kt++) {
        int base = (w * 16 + g) * KSTR + kt * 8 + tg;
        qa[kt][0] = QP[base];
        qa[kt][1] = QP[base + 8 * KSTR];
        qa[kt][2] = QP[base + 4];
        qa[kt][3] = QP[base + 8 * KSTR + 4];
    }

    const unsigned* kg = g_kt + (size_t)kvh * S * HD;
    const unsigned* vg = g_vt + (size_t)kvh * S * HD;

    auto stage = [&](int buf, int kk) {
        unsigned koff = smem_base + (unsigned)(buf * BUFU) * 4;
        unsigned voff = koff + KBUF * 4;
#pragma unroll
        for (int e2 = 0; e2 < 4; e2++) {
            int e = tid + e2 * 256;
            int rr = e >> 4, c = (e & 15) * 4;
            const unsigned* gk = kg + (size_t)(kk + rr) * HD + c;
            const unsigned* gv = vg + (size_t)(kk + rr) * HD + c;
            asm volatile("cp.async.cg.shared.global [%0], [%1], 16;"
                         :: "r"(koff + (unsigned)(rr * KSTR + c) * 4), "l"(gk));
            asm volatile("cp.async.cg.shared.global [%0], [%1], 16;"
                         :: "r"(voff + (unsigned)(rr * VSTR + c) * 4), "l"(gv));
        }
    };

    float oacc[8][4];
#pragma unroll
    for (int nt = 0; nt < 8; nt++)
#pragma unroll
        for (int c = 0; c < 4; c++) oacc[nt][c] = 0.f;

    float m0 = -1e30f, m1 = -1e30f, l0 = 0.f, l1 = 0.f;
    int row0 = q0 + w * 16 + g;
    int row1 = row0 + 8;
    unsigned* Pw = QP + w * 16 * KSTR;

    int nch = (q0 + 128) / 64;
    stage(0, 0);
    asm volatile("cp.async.commit_group;");

    for (int it = 0; it < nch; it++) {
        int kk = it * 64;
        if (it + 1 < nch) {
            stage((it + 1) & 1, kk + 64);
            asm volatile("cp.async.commit_group;");
            asm volatile("cp.async.wait_group 1;");
        } else {
            asm volatile("cp.async.wait_group 0;");
        }
        __syncthreads();

        const unsigned* Ks = sm + (it & 1) * BUFU;
        const unsigned* Vs = Ks + KBUF;

        float sacc[8][4];
#pragma unroll
        for (int nt = 0; nt < 8; nt++) {
#pragma unroll
            for (int c = 0; c < 4; c++) sacc[nt][c] = 0.f;
#pragma unroll
            for (int kt = 0; kt < 8; kt++) {
                int r = (nt * 8 + g) * KSTR + kt * 8 + tg;
                unsigned b[2] = { Ks[r], Ks[r + 4] };
                mma_tf32(sacc[nt], qa[kt], b);
            }
        }

        if (kk + 63 > row0) {
#pragma unroll
            for (int nt = 0; nt < 8; nt++) {
                int col = kk + nt * 8 + 2 * tg;
                if (col     > row0) sacc[nt][0] = -1e30f;
                if (col + 1 > row0) sacc[nt][1] = -1e30f;
                if (col     > row1) sacc[nt][2] = -1e30f;
                if (col + 1 > row1) sacc[nt][3] = -1e30f;
            }
        }

        float mc0 = -1e30f, mc1 = -1e30f;
#pragma unroll
        for (int nt = 0; nt < 8; nt++) {
            mc0 = fmaxf(mc0, fmaxf(sacc[nt][0], sacc[nt][1]));
            mc1 = fmaxf(mc1, fmaxf(sacc[nt][2], sacc[nt][3]));
        }
        mc0 = fmaxf(mc0, __shfl_xor_sync(0xFFFFFFFFu, mc0, 1));
        mc0 = fmaxf(mc0, __shfl_xor_sync(0xFFFFFFFFu, mc0, 2));
        mc1 = fmaxf(mc1, __shfl_xor_sync(0xFFFFFFFFu, mc1, 1));
        mc1 = fmaxf(mc1, __shfl_xor_sync(0xFFFFFFFFu, mc1, 2));

        float mn0 = fmaxf(m0, mc0), mn1 = fmaxf(m1, mc1);
        float cr0 = __expf(m0 - mn0), cr1 = __expf(m1 - mn1);
        l0 *= cr0; l1 *= cr1;
#pragma unroll
        for (int nt = 0; nt < 8; nt++) {
            oacc[nt][0] *= cr0; oacc[nt][1] *= cr0;
            oacc[nt][2] *= cr1; oacc[nt][3] *= cr1;
        }
        m0 = mn0; m1 = mn1;

#pragma unroll
        for (int nt = 0; nt < 8; nt++) {
            float p0 = __expf(sacc[nt][0] - mn0);
            float p1 = __expf(sacc[nt][1] - mn0);
            float p2 = __expf(sacc[nt][2] - mn1);
            float p3 = __expf(sacc[nt][3] - mn1);
            l0 += p0 + p1;
            l1 += p2 + p3;
            int pb = g * KSTR + nt * 8 + 2 * tg;
            *(uint2*)(Pw + pb)            = make_uint2(f2tf(p0), f2tf(p1));
            *(uint2*)(Pw + pb + 8 * KSTR) = make_uint2(f2tf(p2), f2tf(p3));
        }
        __syncwarp();

#pragma unroll
        for (int kt = 0; kt < 8; kt++) {
            unsigned pa[4];
            int pb = g * KSTR + kt * 8 + tg;
            pa[0] = Pw[pb];
            pa[1] = Pw[pb + 8 * KSTR];
            pa[2] = Pw[pb + 4];
            pa[3] = Pw[pb + 8 * KSTR + 4];
#pragma unroll
            for (int nt = 0; nt < 8; nt++) {
                int r = (kt * 8 + tg) * VSTR + nt * 8 + g;
                unsigned b[2] = { Vs[r], Vs[r + 4 * VSTR] };
                mma_tf32(oacc[nt], pa, b);
            }
        }
        __syncthreads();
    }

    l0 += __shfl_xor_sync(0xFFFFFFFFu, l0, 1);
    l0 += __shfl_xor_sync(0xFFFFFFFFu, l0, 2);
    l1 += __shfl_xor_sync(0xFFFFFFFFu, l1, 1);
    l1 += __shfl_xor_sync(0xFFFFFFFFu, l1, 2);
    float inv0 = 1.f / l0, inv1 = 1.f / l1;

    // Fused fp16 hi/lo split epilogue
#pragma unroll
    for (int nt = 0; nt < 8; nt++) {
        int col = h * HD + nt * 8 + 2 * tg;
        {
            float a0 = oacc[nt][0] * inv0, a1 = oacc[nt][1] * inv0;
            __half2 hv = __floats2half2_rn(a0, a1);
            __half2 lv = __floats2half2_rn(a0 - __low2float(hv), a1 - __high2float(hv));
            *(__half2*)(s_at_h + (size_t)row0 * Hdim + col) = hv;
            *(__half2*)(s_at_l + (size_t)row0 * Hdim + col) = lv;
        }
        {
            float a0 = oacc[nt][2] * inv1, a1 = oacc[nt][3] * inv1;
            __half2 hv = __floats2half2_rn(a0, a1);
            __half2 lv = __floats2half2_rn(a0 - __low2float(hv), a1 - __high2float(hv));
            *(__half2*)(s_at_h + (size_t)row1 * Hdim + col) = hv;
            *(__half2*)(s_at_l + (size_t)row1 * Hdim + col) = lv;
        }
    }
}

// ---------------------------------------------------------------------------
// Launch
// ---------------------------------------------------------------------------
extern "C" void kernel_launch(void* const* d_in, const int* in_sizes, int n_in,
                              void* d_out, int out_size)
{
    const float* hs = (const float*)d_in[0];
    const float* Wq = (const float*)d_in[1];
    const float* Wk = (const float*)d_in[2];
    const float* Wv = (const float*)d_in[3];
    const float* Wo = (const float*)d_in[4];
    float* out = (float*)d_out;

    float* qkvp;
    __half *hsh, *hsl, *wah, *woh, *ath, *atl;
    cudaGetSymbolAddress((void**)&qkvp, g_qkv);
    cudaGetSymbolAddress((void**)&hsh, s_hs_h);  cudaGetSymbolAddress((void**)&hsl, s_hs_l);
    cudaGetSymbolAddress((void**)&wah, s_wa_h);
    cudaGetSymbolAddress((void**)&woh, s_wo_h);
    cudaGetSymbolAddress((void**)&ath, s_at_h);  cudaGetSymbolAddress((void**)&atl, s_at_l);

    const int gemm_smem = 2 * STG3 * 4;   // 61440 B
    cudaFuncSetAttribute(gemm_f16x2_nt,
                         cudaFuncAttributeMaxDynamicSharedMemorySize, gemm_smem);
    cudaFuncSetAttribute(flash_attn_tc,
                         cudaFuncAttributeMaxDynamicSharedMemorySize, ATTN_SMEM_B);

    split_all<<<(TOT4 + 255) / 256, 256>>>(
        (const float4*)hs, (const float4*)Wq, (const float4*)Wk,
        (const float4*)Wv, (const float4*)Wo);

    // Fused QKV projection
    gemm_f16x2_nt<<<dim3(NQKV / 128, S / 128), 256, gemm_smem>>>(
        hsh, hsl, wah, qkvp, S, NQKV, Hdim);

    {
        int total = S * (NH + 2 * NKV) * 32;
        rope_conv_kernel<<<(total + 255) / 256, 256>>>();
    }

    flash_attn_tc<<<dim3(S / 128, NH), 256, ATTN_SMEM_B>>>();

    // Output projection
    gemm_f16x2_nt<<<dim3(Hdim / 128, S / 128), 256, gemm_smem>>>(
        ath, atl, woh, out, S, Hdim, Hdim);
}